// round 10
// baseline (speedup 1.0000x reference)
#include <cuda_runtime.h>
#include <cuda_bf16.h>

// TensorRepsTransform: per row n (N=65536, DIM=832)
//   out[0:64)         = t[0:64)                                   (order-0, even)
//   out[64+4s+j)      = sign(det L) * sum_k L[j][k] t[64+4s+k]    (order-1, odd)
//   out[320+16s+4a+b) = sum_{k1,k2} L[a][k1] L[b][k2] t[320+16s+4k1+4k2]  (order-2, even)
//
// R6 body (measured best: one warp/row, 7 front-batched coalesced float4
// loads, 4-lane shuffle groups for order-2) in a PERSISTENT grid-stride loop:
// exactly one resident wave (4 blocks/SM), removing ~13 wave transitions and
// letting iteration i+1's loads overlap iteration i's stores inside each warp.

#define ROW_DIM 832

__global__ __launch_bounds__(256) void trep_kernel(
    const float* __restrict__ tens,
    const float* __restrict__ lfr,
    float* __restrict__ out,
    int nrows, int totwarps)
{
    const int gw0  = (int)((blockIdx.x * 256u + threadIdx.x) >> 5);
    const int lane = threadIdx.x & 31;

    for (int row = gw0; row < nrows; row += totwarps) {
        const float* __restrict__ tr   = tens + (size_t)row * ROW_DIM;
        float* __restrict__       orow = out  + (size_t)row * ROW_DIM;

        // ---- front-batched loads (max per-warp MLP; measured DRAM% lever) ----
        const float4* Lp = (const float4*)(lfr + (size_t)row * 16);
        float4 Lr0 = Lp[0], Lr1 = Lp[1], Lr2 = Lp[2], Lr3 = Lp[3];

        // order-2: 128 float4, 4 per lane (coalesced)
        float4 t0 = __ldcs(((const float4*)(tr + 320)) + lane);
        float4 t1 = __ldcs(((const float4*)(tr + 320)) + lane + 32);
        float4 t2 = __ldcs(((const float4*)(tr + 320)) + lane + 64);
        float4 t3 = __ldcs(((const float4*)(tr + 320)) + lane + 96);

        // order-1: 64 float4, 2 per lane (coalesced)
        float4 v1 = __ldcs(((const float4*)(tr + 64)) + lane);
        float4 v2 = __ldcs(((const float4*)(tr + 64)) + lane + 32);

        // order-0 passthrough: load + immediate store
        if (lane < 16) {
            float4 q0 = __ldcs(((const float4*)tr) + lane);
            __stcs(((float4*)orow) + lane, q0);
        }

        float L00=Lr0.x, L01=Lr0.y, L02=Lr0.z, L03=Lr0.w;
        float L10=Lr1.x, L11=Lr1.y, L12=Lr1.z, L13=Lr1.w;
        float L20=Lr2.x, L21=Lr2.y, L22=Lr2.z, L23=Lr2.w;
        float L30=Lr3.x, L31=Lr3.y, L32=Lr3.z, L33=Lr3.w;

        // ---- det(L) sign ----
        float det =
              (L00*L11 - L01*L10) * (L22*L33 - L23*L32)
            - (L00*L12 - L02*L10) * (L21*L33 - L23*L31)
            + (L00*L13 - L03*L10) * (L21*L32 - L22*L31)
            + (L01*L12 - L02*L11) * (L20*L33 - L23*L30)
            - (L01*L13 - L03*L11) * (L20*L32 - L22*L30)
            + (L02*L13 - L03*L12) * (L20*L31 - L21*L30);
        float sgn = (det > 0.0f) ? 1.0f : ((det < 0.0f) ? -1.0f : 0.0f);

        // ---- order-1: y = sgn * (L v), 2 slots per lane ----
        {
            float4 y;
            y.x = sgn * (L00*v1.x + L01*v1.y + L02*v1.z + L03*v1.w);
            y.y = sgn * (L10*v1.x + L11*v1.y + L12*v1.z + L13*v1.w);
            y.z = sgn * (L20*v1.x + L21*v1.y + L22*v1.z + L23*v1.w);
            y.w = sgn * (L30*v1.x + L31*v1.y + L32*v1.z + L33*v1.w);
            __stcs(((float4*)(orow + 64)) + lane, y);

            y.x = sgn * (L00*v2.x + L01*v2.y + L02*v2.z + L03*v2.w);
            y.y = sgn * (L10*v2.x + L11*v2.y + L12*v2.z + L13*v2.w);
            y.z = sgn * (L20*v2.x + L21*v2.y + L22*v2.z + L23*v2.w);
            y.w = sgn * (L30*v2.x + L31*v2.y + L32*v2.z + L33*v2.w);
            __stcs(((float4*)(orow + 64)) + lane + 32, y);
        }

        // ---- order-2: U = L (T L^T), cooperative in 4-lane groups ----
        // float4 #g of the order-2 block is row (g&3) of slot (g>>2).
        const int r = lane & 3;
        float4 Lrow = (r == 0) ? Lr0 : (r == 1) ? Lr1 : (r == 2) ? Lr2 : Lr3;

        #pragma unroll
        for (int a = 0; a < 4; a++) {
            float4 Ta = (a == 0) ? t0 : (a == 1) ? t1 : (a == 2) ? t2 : t3;

            // B[m] = sum_k L[m][k] * T[r][k]   (local)
            float4 B;
            B.x = L00*Ta.x + L01*Ta.y + L02*Ta.z + L03*Ta.w;
            B.y = L10*Ta.x + L11*Ta.y + L12*Ta.z + L13*Ta.w;
            B.z = L20*Ta.x + L21*Ta.y + L22*Ta.z + L23*Ta.w;
            B.w = L30*Ta.x + L31*Ta.y + L32*Ta.z + L33*Ta.w;

            // U[r][m] = sum_{r'} L[r][r'] * B_{r'}[m]   (width-4 shuffles)
            float4 U = make_float4(0.f, 0.f, 0.f, 0.f);
            #pragma unroll
            for (int rp = 0; rp < 4; rp++) {
                float bx = __shfl_sync(0xffffffffu, B.x, rp, 4);
                float by = __shfl_sync(0xffffffffu, B.y, rp, 4);
                float bz = __shfl_sync(0xffffffffu, B.z, rp, 4);
                float bw = __shfl_sync(0xffffffffu, B.w, rp, 4);
                float c = (rp == 0) ? Lrow.x : (rp == 1) ? Lrow.y
                        : (rp == 2) ? Lrow.z : Lrow.w;
                U.x += c * bx;
                U.y += c * by;
                U.z += c * bz;
                U.w += c * bw;
            }
            __stcs(((float4*)(orow + 320)) + 32 * a + lane, U);
        }
    }
}

extern "C" void kernel_launch(void* const* d_in, const int* in_sizes, int n_in,
                              void* d_out, int out_size)
{
    const float* tens = (const float*)d_in[0];   // (N, 832) float32
    const float* lfr  = (const float*)d_in[1];   // (N, 4, 4) float32
    // d_in[2] = parity_odd mask: compile-time constant of REPS, folded into layout.
    (void)n_in; (void)out_size;

    int nrows = in_sizes[0] / ROW_DIM;           // 65536
    float* out = (float*)d_out;

    // Persistent: one resident wave. 64 regs/thread, 256 thr/block ->
    // 4 blocks/SM on the 64K-reg RF; 148 SMs (sm_100a) -> 592 blocks.
    int nblocks  = 148 * 4;
    int totwarps = nblocks * 8;                  // 8 warps per block

    trep_kernel<<<nblocks, 256>>>(tens, lfr, out, nrows, totwarps);
}

// round 11
// speedup vs baseline: 1.1484x; 1.1484x over previous
#include <cuda_runtime.h>
#include <cuda_bf16.h>

// TensorRepsTransform: per row n (N=65536, DIM=832)
//   out[0:64)         = t[0:64)                                   (order-0, even)
//   out[64+4s+j)      = sign(det L) * sum_k L[j][k] t[64+4s+k]    (order-1, odd)
//   out[320+16s+4a+b) = sum_{k1,k2} L[a][k1] L[b][k2] t[320+16s+4k1+4k2]  (order-2, even)
//
// R6 config (measured best: one warp/row, 7 front-batched coalesced float4
// loads, 4-lane shuffle groups for order-2) with DEFAULT cache policy:
// write-back stores let replay i's dirty output lines be overwritten in L2 by
// replay i+1 (write elision), and default loads keep replay-reusable input
// lines resident — both were defeated by the previous .cs streaming hints.

#define ROW_DIM 832

__global__ __launch_bounds__(256) void trep_kernel(
    const float* __restrict__ tens,
    const float* __restrict__ lfr,
    float* __restrict__ out,
    int nrows)
{
    const int gwarp = (int)((blockIdx.x * 256u + threadIdx.x) >> 5);
    const int lane  = threadIdx.x & 31;
    if (gwarp >= nrows) return;

    const float* __restrict__ tr   = tens + (size_t)gwarp * ROW_DIM;
    float* __restrict__       orow = out  + (size_t)gwarp * ROW_DIM;

    // ---- front-batched loads (max per-warp MLP; measured DRAM% lever) ----
    // L first: det/sgn feeds the earliest stores.
    const float4* Lp = (const float4*)(lfr + (size_t)gwarp * 16);
    float4 Lr0 = Lp[0], Lr1 = Lp[1], Lr2 = Lp[2], Lr3 = Lp[3];

    // order-2: 128 float4, 4 per lane (coalesced)
    float4 t0 = ((const float4*)(tr + 320))[lane];
    float4 t1 = ((const float4*)(tr + 320))[lane + 32];
    float4 t2 = ((const float4*)(tr + 320))[lane + 64];
    float4 t3 = ((const float4*)(tr + 320))[lane + 96];

    // order-1: 64 float4, 2 per lane (coalesced)
    float4 v1 = ((const float4*)(tr + 64))[lane];
    float4 v2 = ((const float4*)(tr + 64))[lane + 32];

    // order-0 passthrough: load + immediate store
    if (lane < 16) {
        float4 q0 = ((const float4*)tr)[lane];
        ((float4*)orow)[lane] = q0;
    }

    float L00=Lr0.x, L01=Lr0.y, L02=Lr0.z, L03=Lr0.w;
    float L10=Lr1.x, L11=Lr1.y, L12=Lr1.z, L13=Lr1.w;
    float L20=Lr2.x, L21=Lr2.y, L22=Lr2.z, L23=Lr2.w;
    float L30=Lr3.x, L31=Lr3.y, L32=Lr3.z, L33=Lr3.w;

    // ---- det(L) sign ----
    float det =
          (L00*L11 - L01*L10) * (L22*L33 - L23*L32)
        - (L00*L12 - L02*L10) * (L21*L33 - L23*L31)
        + (L00*L13 - L03*L10) * (L21*L32 - L22*L31)
        + (L01*L12 - L02*L11) * (L20*L33 - L23*L30)
        - (L01*L13 - L03*L11) * (L20*L32 - L22*L30)
        + (L02*L13 - L03*L12) * (L20*L31 - L21*L30);
    float sgn = (det > 0.0f) ? 1.0f : ((det < 0.0f) ? -1.0f : 0.0f);

    // ---- order-1: y = sgn * (L v), 2 slots per lane ----
    {
        float4 y;
        y.x = sgn * (L00*v1.x + L01*v1.y + L02*v1.z + L03*v1.w);
        y.y = sgn * (L10*v1.x + L11*v1.y + L12*v1.z + L13*v1.w);
        y.z = sgn * (L20*v1.x + L21*v1.y + L22*v1.z + L23*v1.w);
        y.w = sgn * (L30*v1.x + L31*v1.y + L32*v1.z + L33*v1.w);
        ((float4*)(orow + 64))[lane] = y;

        y.x = sgn * (L00*v2.x + L01*v2.y + L02*v2.z + L03*v2.w);
        y.y = sgn * (L10*v2.x + L11*v2.y + L12*v2.z + L13*v2.w);
        y.z = sgn * (L20*v2.x + L21*v2.y + L22*v2.z + L23*v2.w);
        y.w = sgn * (L30*v2.x + L31*v2.y + L32*v2.z + L33*v2.w);
        ((float4*)(orow + 64))[lane + 32] = y;
    }

    // ---- order-2: U = L (T L^T), cooperative in 4-lane groups ----
    // float4 #g of the order-2 block is row (g&3) of slot (g>>2).
    const int r = lane & 3;
    float4 Lrow = (r == 0) ? Lr0 : (r == 1) ? Lr1 : (r == 2) ? Lr2 : Lr3;

    #pragma unroll
    for (int a = 0; a < 4; a++) {
        float4 Ta = (a == 0) ? t0 : (a == 1) ? t1 : (a == 2) ? t2 : t3;

        // B[m] = sum_k L[m][k] * T[r][k]   (local)
        float4 B;
        B.x = L00*Ta.x + L01*Ta.y + L02*Ta.z + L03*Ta.w;
        B.y = L10*Ta.x + L11*Ta.y + L12*Ta.z + L13*Ta.w;
        B.z = L20*Ta.x + L21*Ta.y + L22*Ta.z + L23*Ta.w;
        B.w = L30*Ta.x + L31*Ta.y + L32*Ta.z + L33*Ta.w;

        // U[r][m] = sum_{r'} L[r][r'] * B_{r'}[m]   (width-4 shuffles)
        float4 U = make_float4(0.f, 0.f, 0.f, 0.f);
        #pragma unroll
        for (int rp = 0; rp < 4; rp++) {
            float bx = __shfl_sync(0xffffffffu, B.x, rp, 4);
            float by = __shfl_sync(0xffffffffu, B.y, rp, 4);
            float bz = __shfl_sync(0xffffffffu, B.z, rp, 4);
            float bw = __shfl_sync(0xffffffffu, B.w, rp, 4);
            float c = (rp == 0) ? Lrow.x : (rp == 1) ? Lrow.y
                    : (rp == 2) ? Lrow.z : Lrow.w;
            U.x += c * bx;
            U.y += c * by;
            U.z += c * bz;
            U.w += c * bw;
        }
        ((float4*)(orow + 320))[32 * a + lane] = U;
    }
}

extern "C" void kernel_launch(void* const* d_in, const int* in_sizes, int n_in,
                              void* d_out, int out_size)
{
    const float* tens = (const float*)d_in[0];   // (N, 832) float32
    const float* lfr  = (const float*)d_in[1];   // (N, 4, 4) float32
    // d_in[2] = parity_odd mask: compile-time constant of REPS, folded into layout.
    (void)n_in; (void)out_size;

    int nrows = in_sizes[0] / ROW_DIM;           // 65536
    float* out = (float*)d_out;

    int nblocks = (nrows * 32 + 255) / 256;      // one warp per row
    trep_kernel<<<nblocks, 256>>>(tens, lfr, out, nrows);
}

// round 12
// speedup vs baseline: 1.1489x; 1.0005x over previous
#include <cuda_runtime.h>
#include <cuda_bf16.h>

// TensorRepsTransform: per row n (N=65536, DIM=832)
//   out[0:64)         = t[0:64)                                   (order-0, even)
//   out[64+4s+j)      = sign(det L) * sum_k L[j][k] t[64+4s+k]    (order-1, odd)
//   out[320+16s+4a+b) = sum_{k1,k2} L[a][k1] L[b][k2] t[320+16s+4k1+4k2]  (order-2, even)
//
// One warp per row, 256-bit (v8.f32) global loads/stores (sm_100 LDG.E.256):
// 1024B warp-requests halve DRAM request interleave points and LSU issue
// count; order-2 exchange shrinks to pair-lane shfl_xor (16 vs 64 shuffles).

#define ROW_DIM 832

__device__ __forceinline__ void ldg_v8(const float* p, float4& a, float4& b) {
    asm("ld.global.v8.f32 {%0,%1,%2,%3,%4,%5,%6,%7}, [%8];"
        : "=f"(a.x), "=f"(a.y), "=f"(a.z), "=f"(a.w),
          "=f"(b.x), "=f"(b.y), "=f"(b.z), "=f"(b.w)
        : "l"(p));
}
__device__ __forceinline__ void stg_v8(float* p, const float4& a, const float4& b) {
    asm volatile("st.global.v8.f32 [%0], {%1,%2,%3,%4,%5,%6,%7,%8};"
        :: "l"(p),
           "f"(a.x), "f"(a.y), "f"(a.z), "f"(a.w),
           "f"(b.x), "f"(b.y), "f"(b.z), "f"(b.w)
        : "memory");
}

__global__ __launch_bounds__(256) void trep_kernel(
    const float* __restrict__ tens,
    const float* __restrict__ lfr,
    float* __restrict__ out,
    int nrows)
{
    const int gwarp = (int)((blockIdx.x * 256u + threadIdx.x) >> 5);
    const int lane  = threadIdx.x & 31;
    if (gwarp >= nrows) return;

    const float* __restrict__ tr   = tens + (size_t)gwarp * ROW_DIM;
    float* __restrict__       orow = out  + (size_t)gwarp * ROW_DIM;

    // ---- front-batched loads (one warp covers the whole row) ----
    // order-2: 64 v8-chunks (8 floats each), 2 per lane
    float4 tA0, tA1, tB0, tB1;
    ldg_v8(tr + 320 + 8 * lane,         tA0, tA1);
    ldg_v8(tr + 320 + 8 * (lane + 32),  tB0, tB1);

    // order-1: 32 v8-chunks = 2 slots per lane
    float4 v1, v2;
    ldg_v8(tr + 64 + 8 * lane, v1, v2);

    // L: warp-uniform -> broadcast
    const float4* Lp = (const float4*)(lfr + (size_t)gwarp * 16);
    float4 Lr0 = Lp[0], Lr1 = Lp[1], Lr2 = Lp[2], Lr3 = Lp[3];

    // order-0 passthrough: 8 v8-chunks, lanes 0..7
    if (lane < 8) {
        float4 q0, q1;
        ldg_v8(tr + 8 * lane, q0, q1);
        stg_v8(orow + 8 * lane, q0, q1);
    }

    float L00=Lr0.x, L01=Lr0.y, L02=Lr0.z, L03=Lr0.w;
    float L10=Lr1.x, L11=Lr1.y, L12=Lr1.z, L13=Lr1.w;
    float L20=Lr2.x, L21=Lr2.y, L22=Lr2.z, L23=Lr2.w;
    float L30=Lr3.x, L31=Lr3.y, L32=Lr3.z, L33=Lr3.w;

    // ---- det(L) sign ----
    float det =
          (L00*L11 - L01*L10) * (L22*L33 - L23*L32)
        - (L00*L12 - L02*L10) * (L21*L33 - L23*L31)
        + (L00*L13 - L03*L10) * (L21*L32 - L22*L31)
        + (L01*L12 - L02*L11) * (L20*L33 - L23*L30)
        - (L01*L13 - L03*L11) * (L20*L32 - L22*L30)
        + (L02*L13 - L03*L12) * (L20*L31 - L21*L30);
    float sgn = (det > 0.0f) ? 1.0f : ((det < 0.0f) ? -1.0f : 0.0f);

    // ---- order-1: y = sgn * (L v), slots 2*lane and 2*lane+1 in one v8 ----
    {
        float4 y1, y2;
        y1.x = sgn * (L00*v1.x + L01*v1.y + L02*v1.z + L03*v1.w);
        y1.y = sgn * (L10*v1.x + L11*v1.y + L12*v1.z + L13*v1.w);
        y1.z = sgn * (L20*v1.x + L21*v1.y + L22*v1.z + L23*v1.w);
        y1.w = sgn * (L30*v1.x + L31*v1.y + L32*v1.z + L33*v1.w);
        y2.x = sgn * (L00*v2.x + L01*v2.y + L02*v2.z + L03*v2.w);
        y2.y = sgn * (L10*v2.x + L11*v2.y + L12*v2.z + L13*v2.w);
        y2.z = sgn * (L20*v2.x + L21*v2.y + L22*v2.z + L23*v2.w);
        y2.w = sgn * (L30*v2.x + L31*v2.y + L32*v2.z + L33*v2.w);
        stg_v8(orow + 64 + 8 * lane, y1, y2);
    }

    // ---- order-2: U = L (T L^T), pair-lane cooperative ----
    // v8 chunk #c holds rows {2p, 2p+1} (p = c&1 = lane&1) of slot c>>1.
    // Partner lane (lane^1) holds the other two rows of the same slot.
    const int p = lane & 1;
    const float4 Lq0 = p ? Lr2 : Lr0;   // L row 2p
    const float4 Lq1 = p ? Lr3 : Lr1;   // L row 2p+1

    #pragma unroll
    for (int a = 0; a < 2; a++) {
        float4 Ta0 = (a == 0) ? tA0 : tB0;   // T row 2p
        float4 Ta1 = (a == 0) ? tA1 : tB1;   // T row 2p+1

        // B[r][m] = sum_k L[m][k] T[r][k]  for local rows r = 2p, 2p+1
        float4 B0, B1;
        B0.x = L00*Ta0.x + L01*Ta0.y + L02*Ta0.z + L03*Ta0.w;
        B0.y = L10*Ta0.x + L11*Ta0.y + L12*Ta0.z + L13*Ta0.w;
        B0.z = L20*Ta0.x + L21*Ta0.y + L22*Ta0.z + L23*Ta0.w;
        B0.w = L30*Ta0.x + L31*Ta0.y + L32*Ta0.z + L33*Ta0.w;
        B1.x = L00*Ta1.x + L01*Ta1.y + L02*Ta1.z + L03*Ta1.w;
        B1.y = L10*Ta1.x + L11*Ta1.y + L12*Ta1.z + L13*Ta1.w;
        B1.z = L20*Ta1.x + L21*Ta1.y + L22*Ta1.z + L23*Ta1.w;
        B1.w = L30*Ta1.x + L31*Ta1.y + L32*Ta1.z + L33*Ta1.w;

        // partner's two B rows (8 shuffles)
        float4 C0, C1;
        C0.x = __shfl_xor_sync(0xffffffffu, B0.x, 1);
        C0.y = __shfl_xor_sync(0xffffffffu, B0.y, 1);
        C0.z = __shfl_xor_sync(0xffffffffu, B0.z, 1);
        C0.w = __shfl_xor_sync(0xffffffffu, B0.w, 1);
        C1.x = __shfl_xor_sync(0xffffffffu, B1.x, 1);
        C1.y = __shfl_xor_sync(0xffffffffu, B1.y, 1);
        C1.z = __shfl_xor_sync(0xffffffffu, B1.z, 1);
        C1.w = __shfl_xor_sync(0xffffffffu, B1.w, 1);

        // assemble B rows 0..3 of the slot
        float4 R0 = p ? C0 : B0;
        float4 R1 = p ? C1 : B1;
        float4 R2 = p ? B0 : C0;
        float4 R3 = p ? B1 : C1;

        // U[q][m] = sum_{r'} L[q][r'] * R_{r'}[m]   for q = 2p, 2p+1
        float4 U0, U1;
        U0.x = Lq0.x*R0.x + Lq0.y*R1.x + Lq0.z*R2.x + Lq0.w*R3.x;
        U0.y = Lq0.x*R0.y + Lq0.y*R1.y + Lq0.z*R2.y + Lq0.w*R3.y;
        U0.z = Lq0.x*R0.z + Lq0.y*R1.z + Lq0.z*R2.z + Lq0.w*R3.z;
        U0.w = Lq0.x*R0.w + Lq0.y*R1.w + Lq0.z*R2.w + Lq0.w*R3.w;
        U1.x = Lq1.x*R0.x + Lq1.y*R1.x + Lq1.z*R2.x + Lq1.w*R3.x;
        U1.y = Lq1.x*R0.y + Lq1.y*R1.y + Lq1.z*R2.y + Lq1.w*R3.y;
        U1.z = Lq1.x*R0.z + Lq1.y*R1.z + Lq1.z*R2.z + Lq1.w*R3.z;
        U1.w = Lq1.x*R0.w + Lq1.y*R1.w + Lq1.z*R2.w + Lq1.w*R3.w;

        stg_v8(orow + 320 + 8 * (32 * a + lane), U0, U1);
    }
}

extern "C" void kernel_launch(void* const* d_in, const int* in_sizes, int n_in,
                              void* d_out, int out_size)
{
    const float* tens = (const float*)d_in[0];   // (N, 832) float32
    const float* lfr  = (const float*)d_in[1];   // (N, 4, 4) float32
    // d_in[2] = parity_odd mask: compile-time constant of REPS, folded into layout.
    (void)n_in; (void)out_size;

    int nrows = in_sizes[0] / ROW_DIM;           // 65536
    float* out = (float*)d_out;

    int nblocks = (nrows * 32 + 255) / 256;      // one warp per row
    trep_kernel<<<nblocks, 256>>>(tens, lfr, out, nrows);
}